// round 13
// baseline (speedup 1.0000x reference)
#include <cuda_runtime.h>
#include <cuda_bf16.h>
#include <math.h>

#define BB   4
#define TIN  16
#define OC3  48
#define DD   31
#define HH   128
#define WW   128
#define HWSZ 16384
#define MCH  496    // 16*31 combined channels
#define NCH  31     // attention channels

typedef unsigned long long u64;

__device__ __forceinline__ u64 pack2(float x, float y) {
    u64 r; asm("mov.b64 %0, {%1, %2};" : "=l"(r) : "f"(x), "f"(y)); return r;
}
__device__ __forceinline__ float2 unpack2(u64 v) {
    float2 r; asm("mov.b64 {%0, %1}, %2;" : "=f"(r.x), "=f"(r.y) : "l"(v)); return r;
}
__device__ __forceinline__ void fma2(u64& d, u64 a, u64 b) {
    asm("fma.rn.f32x2 %0, %1, %2, %0;" : "+l"(d) : "l"(a), "l"(b));
}

// ---------------- scratch --------------------------------------------------
__device__ float g_q[(size_t)BB * MCH * HWSZ];
__device__ float g_k[(size_t)BB * MCH * HWSZ];
__device__ float g_v[(size_t)BB * MCH * HWSZ];
__device__ float g_sqk[BB * NCH * NCH];
__device__ float g_nq[BB * NCH];
__device__ float g_nk[BB * NCH];
__device__ float g_attn[BB * NCH * NCH];

// ---------------- K0: zero accumulators ------------------------------------
__global__ void k0_zero() {
    int i = threadIdx.x + blockIdx.x * blockDim.x;
    if (i < BB * NCH * NCH) g_sqk[i] = 0.f;
    if (i < BB * NCH) { g_nq[i] = 0.f; g_nk[i] = 0.f; }
}

// ---------------- K1: fused pointwise QKV + depthwise 3x3 ------------------
// tile 32 wide x 16 tall. Halo: cols [w0-2, w0+34) = 36 (18 ALIGNED pairs),
// rows [h0-1, h0+17) = 18. 324 pairs total; 256 threads, 68 take a 2nd slot.
#define HLW 36
#define NPAIR 324

__device__ __forceinline__ void k1_load_slot(u64* xr, int pp, int b, int d,
                                             int h0, int w0, const float* __restrict__ x) {
    int y = pp / 18;
    int px = pp - y * 18;
    int gh = h0 + y - 1;
    int gw0 = w0 + 2 * px - 2;            // even -> 8B-aligned pairs
    if (gh >= 0 && gh < HH && gw0 >= 0 && gw0 < WW - 1) {
        const float* xp = x + ((size_t)(b * TIN) * DD + d) * HWSZ + gh * WW + gw0;
#pragma unroll
        for (int i = 0; i < 16; i++) { xr[i] = *(const u64*)xp; xp += DD * HWSZ; }
    } else {
#pragma unroll
        for (int i = 0; i < 16; i++) xr[i] = 0ULL;
    }
}

__global__ void __launch_bounds__(256, 2)
k1_qkv(const float* __restrict__ x, const float* __restrict__ wqkv,
       const float* __restrict__ wdw) {
    __shared__ float2 wq2[OC3][16];
    __shared__ float2 wd2[OC3][9];
    __shared__ __align__(16) float pws[2][HLW * 18];   // 648 each

    const int tid = threadIdx.x;
    const int bd = blockIdx.y;
    const int b = bd / DD, d = bd - b * DD;
    const int tx = blockIdx.x & 3, ty = blockIdx.x >> 2;
    const int h0 = ty * 16, w0 = tx * 32;

    for (int i = tid; i < OC3 * 16; i += 256) {
        float w = wqkv[i]; wq2[i >> 4][i & 15] = make_float2(w, w);
    }
    for (int i = tid; i < OC3 * 9; i += 256) {
        float w = wdw[i]; wd2[i / 9][i % 9] = make_float2(w, w);
    }

    u64 xr0[16], xr1[16];
    k1_load_slot(xr0, tid, b, d, h0, w0, x);
    const bool slot1 = (tid < NPAIR - 256);
    if (slot1) k1_load_slot(xr1, tid + 256, b, d, h0, w0, x);

    const int oy = tid >> 4;
    const int ox = (tid & 15) * 2;

    __syncthreads();

    for (int oc = 0; oc < OC3; oc++) {
        float* pwb = pws[oc & 1];
        // pointwise from registers
        {
            u64 acc = 0ULL;
#pragma unroll
            for (int i = 0; i < 16; i++) fma2(acc, xr0[i], *(const u64*)&wq2[oc][i]);
            *(u64*)&pwb[2 * tid] = acc;
            if (slot1) {
                u64 acc1 = 0ULL;
#pragma unroll
                for (int i = 0; i < 16; i++) fma2(acc1, xr1[i], *(const u64*)&wq2[oc][i]);
                *(u64*)&pwb[2 * (tid + 256)] = acc1;
            }
        }
        __syncthreads();
        // depthwise 3x3: taps at halo cols ox+1..ox+4 (halo col0 = w0-2)
        u64 acc = 0ULL;
#pragma unroll
        for (int dy = 0; dy < 3; dy++) {
            const float* row = pwb + (oy + dy) * HLW + ox;
            u64 av = *(const u64*)row;          // hx ox,   ox+1
            u64 bv = *(const u64*)(row + 2);    // hx ox+2, ox+3
            u64 cv = *(const u64*)(row + 4);    // hx ox+4, ox+5
            u64 mv1 = (av >> 32) | (bv << 32);  // hx ox+1, ox+2  (left tap)
            u64 mv2 = (bv >> 32) | (cv << 32);  // hx ox+3, ox+4  (right tap)
            fma2(acc, mv1, *(const u64*)&wd2[oc][3 * dy + 0]);
            fma2(acc, bv,  *(const u64*)&wd2[oc][3 * dy + 1]);
            fma2(acc, mv2, *(const u64*)&wd2[oc][3 * dy + 2]);
        }
        float* dst; int m;
        if (oc < 16)      { dst = g_q; m = oc * DD + d; }
        else if (oc < 32) { dst = g_k; m = (oc - 16) * DD + d; }
        else              { dst = g_v; m = (oc - 32) * DD + d; }
        *(u64*)&dst[((size_t)(b * MCH) + m) * HWSZ + (h0 + oy) * WW + w0 + ox] = acc;
        // no second barrier: double-buffered pws
    }
}

// ---------------- K2: Gram matrix + norms ----------------------------------
// 256 blocks (64 px-chunks x 4 batches). 256 threads: kg(8) x tc2(8) x tc1(4).
#define K2PITCH 260
#define SMEM2 (2 * 32 * K2PITCH * 4)

__global__ void __launch_bounds__(256, 2) k2_gram() {
    extern __shared__ float sm2[];
    float* qs = sm2;                    // [32][260]
    float* ks = sm2 + 32 * K2PITCH;     // [32][260]

    const int tid = threadIdx.x;
    const int kg  = tid & 7;
    const int tc2 = (tid >> 3) & 7;
    const int tc1 = tid >> 6;
    const int b = blockIdx.y;
    const int hw0 = blockIdx.x * 256;

    const int lrow = tid >> 3;
    const int lc8  = tid & 7;

    u64 acc[32];
#pragma unroll
    for (int i = 0; i < 32; i++) acc[i] = 0ULL;
    float nq_acc = 0.f, nk_acc = 0.f;

    for (int r = 0; r < 16; r++) {
        if (r) __syncthreads();
        {
            const bool valid = (lrow < NCH);
            size_t goff = ((size_t)(b * MCH) + 16 * lrow + r) * HWSZ + hw0;
#pragma unroll
            for (int kk = 0; kk < 8; kk++) {
                int f4 = lc8 + 8 * kk;
                float4 qv = make_float4(0.f, 0.f, 0.f, 0.f);
                float4 kv = make_float4(0.f, 0.f, 0.f, 0.f);
                if (valid) {
                    qv = *(const float4*)&g_q[goff + 4 * f4];
                    kv = *(const float4*)&g_k[goff + 4 * f4];
                }
                *(float4*)&qs[lrow * K2PITCH + 4 * f4] = qv;
                *(float4*)&ks[lrow * K2PITCH + 4 * f4] = kv;
                nq_acc += qv.x * qv.x + qv.y * qv.y + qv.z * qv.z + qv.w * qv.w;
                nk_acc += kv.x * kv.x + kv.y * kv.y + kv.z * kv.z + kv.w * kv.w;
            }
        }
        __syncthreads();
        for (int jj = 0; jj < 16; jj++) {
            int px = 2 * kg + 16 * jj;
            u64 qa[8], kv[4];
#pragma unroll
            for (int a = 0; a < 8; a++) qa[a] = *(const u64*)&qs[(tc1 * 8 + a) * K2PITCH + px];
#pragma unroll
            for (int c = 0; c < 4; c++) kv[c] = *(const u64*)&ks[(tc2 * 4 + c) * K2PITCH + px];
#pragma unroll
            for (int a = 0; a < 8; a++)
#pragma unroll
                for (int c = 0; c < 4; c++)
                    fma2(acc[a * 4 + c], qa[a], kv[c]);
        }
    }

    nq_acc += __shfl_xor_sync(0xffffffffu, nq_acc, 1);
    nq_acc += __shfl_xor_sync(0xffffffffu, nq_acc, 2);
    nq_acc += __shfl_xor_sync(0xffffffffu, nq_acc, 4);
    nk_acc += __shfl_xor_sync(0xffffffffu, nk_acc, 1);
    nk_acc += __shfl_xor_sync(0xffffffffu, nk_acc, 2);
    nk_acc += __shfl_xor_sync(0xffffffffu, nk_acc, 4);
    if (lc8 == 0 && lrow < NCH) {
        atomicAdd(&g_nq[b * NCH + lrow], nq_acc);
        atomicAdd(&g_nk[b * NCH + lrow], nk_acc);
    }

#pragma unroll
    for (int e = 0; e < 32; e++) {
        float2 f = unpack2(acc[e]);
        float s = f.x + f.y;
        s += __shfl_xor_sync(0xffffffffu, s, 1);
        s += __shfl_xor_sync(0xffffffffu, s, 2);
        s += __shfl_xor_sync(0xffffffffu, s, 4);
        if (kg == 0) {
            int row = tc1 * 8 + (e >> 2);
            int col = tc2 * 4 + (e & 3);
            if (row < NCH && col < NCH)
                atomicAdd(&g_sqk[b * NCH * NCH + row * NCH + col], s);
        }
    }
}

// ---------------- K3: softmax (one block per output row) --------------------
__global__ void k3_softmax(const float* __restrict__ temperature) {
    const int b = blockIdx.y, c1 = blockIdx.x, lane = threadIdx.x;
    const float temp = temperature[0];
    float nq = fmaxf(sqrtf(g_nq[b * NCH + c1]), 1e-12f);
    float logit = -1e30f;
    if (lane < NCH) {
        float nk = fmaxf(sqrtf(g_nk[b * NCH + lane]), 1e-12f);
        logit = g_sqk[(b * NCH + c1) * NCH + lane] / (nq * nk) * temp;
    }
    float mx = logit;
#pragma unroll
    for (int s = 16; s; s >>= 1) mx = fmaxf(mx, __shfl_xor_sync(0xffffffffu, mx, s));
    float e = (lane < NCH) ? expf(logit - mx) : 0.f;
    float sum = e;
#pragma unroll
    for (int s = 16; s; s >>= 1) sum += __shfl_xor_sync(0xffffffffu, sum, s);
    if (lane < NCH) g_attn[(b * NCH + c1) * NCH + lane] = e / sum;
}

// ---------------- K4: out = attn @ V then 16x16 projection ------------------
#define OAPITCH 32
#define SMEM4 ((MCH * OAPITCH) * 4 + (NCH * 32) * 8 + 256 * 4)

__global__ void __launch_bounds__(256, 2)
k4_out(const float* __restrict__ wproj, float* __restrict__ out) {
    extern __shared__ float sm4[];
    float* oa = sm4;                                  // [496][32]
    float2* attn2 = (float2*)(sm4 + MCH * OAPITCH);   // [31][32] dup pairs
    float* wp_s = sm4 + MCH * OAPITCH + NCH * 32 * 2; // [256]

    const int tid = threadIdx.x;
    const int b = blockIdx.y;
    const int hw0 = blockIdx.x * 32;

    for (int i = tid; i < NCH * NCH; i += 256) {
        int c1 = i / NCH, dc = i - c1 * NCH;
        float a = g_attn[b * NCH * NCH + i];
        attn2[c1 * 32 + dc] = make_float2(a, a);
    }
    wp_s[tid] = wproj[tid];
    __syncthreads();

    // ---- stage 1: oa[16c+r][px] = sum_dc attn[c][dc] * v[16dc+r][px]
    {
        const int pxp = tid & 15, r = tid >> 4;
        const float* vbase = g_v + ((size_t)(b * MCH) + r) * HWSZ + hw0 + 2 * pxp;
        u64 acc[31];
#pragma unroll
        for (int c = 0; c < 31; c++) acc[c] = 0ULL;

        u64 v0 = *(const u64*)(vbase);
        u64 v1 = *(const u64*)(vbase + 16 * HWSZ);
        for (int j = 0; j < 15; j++) {
            int dc = 2 * j;
            u64 n0 = 0ULL, n1 = 0ULL;
            if (j < 14) {
                n0 = *(const u64*)(vbase + (size_t)16 * (dc + 2) * HWSZ);
                n1 = *(const u64*)(vbase + (size_t)16 * (dc + 3) * HWSZ);
            } else {
                n0 = *(const u64*)(vbase + (size_t)16 * 30 * HWSZ);
            }
#pragma unroll
            for (int c = 0; c < 31; c++) {
                ulonglong2 at = *(const ulonglong2*)&attn2[c * 32 + dc];
                fma2(acc[c], v0, at.x);
                fma2(acc[c], v1, at.y);
            }
            v0 = n0; v1 = n1;
        }
#pragma unroll
        for (int c = 0; c < 31; c++) {
            u64 a30 = *(const u64*)&attn2[c * 32 + 30];
            fma2(acc[c], v0, a30);
        }
#pragma unroll
        for (int c = 0; c < 31; c++)
            *(u64*)&oa[(16 * c + r) * OAPITCH + 2 * pxp] = acc[c];
    }
    __syncthreads();

    // ---- stage 2: out[o*31+ds][px] = sum_i wp[o][i] * oa[i*31+ds][px]
    {
        const int pxp = tid & 15;
        const int oo = (tid >> 4) & 7;
        const int dsg = tid >> 7;
        const int o0 = 2 * oo, o1 = 2 * oo + 1;
        u64 wpa[16], wpb[16];
#pragma unroll
        for (int i = 0; i < 16; i++) {
            float wa = wp_s[o0 * 16 + i], wb = wp_s[o1 * 16 + i];
            wpa[i] = pack2(wa, wa);
            wpb[i] = pack2(wb, wb);
        }
        for (int ds = dsg; ds < NCH; ds += 2) {
            u64 a0 = 0ULL, a1 = 0ULL;
#pragma unroll
            for (int i = 0; i < 16; i++) {
                u64 ov = *(const u64*)&oa[(i * NCH + ds) * OAPITCH + 2 * pxp];
                fma2(a0, ov, wpa[i]);
                fma2(a1, ov, wpb[i]);
            }
            size_t obase = ((size_t)((b * 16 + o0) * DD + ds)) * HWSZ + hw0 + 2 * pxp;
            *(u64*)&out[obase] = a0;
            *(u64*)&out[obase + (size_t)DD * HWSZ] = a1;
        }
    }
}

// ---------------- launch -----------------------------------------------------
extern "C" void kernel_launch(void* const* d_in, const int* in_sizes, int n_in,
                              void* d_out, int out_size) {
    const float* x     = (const float*)d_in[0];
    const float* wqkv  = (const float*)d_in[1];
    const float* wdw   = (const float*)d_in[2];
    const float* wproj = (const float*)d_in[3];
    const float* temp  = (const float*)d_in[4];
    float* out = (float*)d_out;

    cudaFuncSetAttribute(k2_gram, cudaFuncAttributeMaxDynamicSharedMemorySize, SMEM2);
    cudaFuncSetAttribute(k4_out,  cudaFuncAttributeMaxDynamicSharedMemorySize, SMEM4);

    k0_zero<<<16, 256>>>();

    dim3 g1(32, BB * DD);
    k1_qkv<<<g1, 256>>>(x, wqkv, wdw);

    dim3 g2(64, BB);
    k2_gram<<<g2, 256, SMEM2>>>();

    dim3 g3(NCH, BB);
    k3_softmax<<<g3, 32>>>(temp);

    dim3 g4(HWSZ / 32, BB);
    k4_out<<<g4, 256, SMEM4>>>(wproj, out);
}

// round 14
// speedup vs baseline: 1.0014x; 1.0014x over previous
#include <cuda_runtime.h>
#include <cuda_bf16.h>
#include <math.h>

#define BB   4
#define TIN  16
#define OC3  48
#define DD   31
#define HH   128
#define WW   128
#define HWSZ 16384
#define MCH  496    // 16*31 combined channels
#define NCH  31     // attention channels

typedef unsigned long long u64;

__device__ __forceinline__ u64 pack2(float x, float y) {
    u64 r; asm("mov.b64 %0, {%1, %2};" : "=l"(r) : "f"(x), "f"(y)); return r;
}
__device__ __forceinline__ float2 unpack2(u64 v) {
    float2 r; asm("mov.b64 {%0, %1}, %2;" : "=f"(r.x), "=f"(r.y) : "l"(v)); return r;
}
__device__ __forceinline__ void fma2(u64& d, u64 a, u64 b) {
    asm("fma.rn.f32x2 %0, %1, %2, %0;" : "+l"(d) : "l"(a), "l"(b));
}

// ---------------- scratch --------------------------------------------------
__device__ float g_q[(size_t)BB * MCH * HWSZ];
__device__ float g_k[(size_t)BB * MCH * HWSZ];
__device__ float g_v[(size_t)BB * MCH * HWSZ];
__device__ float g_sqk[BB * NCH * NCH];
__device__ float g_nq[BB * NCH];
__device__ float g_nk[BB * NCH];
__device__ float g_attn[BB * NCH * NCH];

// ---------------- K0: zero accumulators ------------------------------------
__global__ void k0_zero() {
    int i = threadIdx.x + blockIdx.x * blockDim.x;
    if (i < BB * NCH * NCH) g_sqk[i] = 0.f;
    if (i < BB * NCH) { g_nq[i] = 0.f; g_nk[i] = 0.f; }
}

// ---------------- K1: fused pointwise QKV + depthwise 3x3 ------------------
// tile 32 wide x 16 tall. Halo: cols [w0-2, w0+34) = 36 (18 ALIGNED pairs),
// rows [h0-1, h0+17) = 18. 324 pairs total; 256 threads, 68 take a 2nd slot.
#define HLW 36
#define NPAIR 324

__device__ __forceinline__ void k1_load_slot(u64* xr, int pp, int b, int d,
                                             int h0, int w0, const float* __restrict__ x) {
    int y = pp / 18;
    int px = pp - y * 18;
    int gh = h0 + y - 1;
    int gw0 = w0 + 2 * px - 2;            // even -> 8B-aligned pairs
    if (gh >= 0 && gh < HH && gw0 >= 0 && gw0 < WW - 1) {
        const float* xp = x + ((size_t)(b * TIN) * DD + d) * HWSZ + gh * WW + gw0;
#pragma unroll
        for (int i = 0; i < 16; i++) { xr[i] = *(const u64*)xp; xp += DD * HWSZ; }
    } else {
#pragma unroll
        for (int i = 0; i < 16; i++) xr[i] = 0ULL;
    }
}

__global__ void __launch_bounds__(256, 2)
k1_qkv(const float* __restrict__ x, const float* __restrict__ wqkv,
       const float* __restrict__ wdw) {
    __shared__ float2 wq2[OC3][16];
    __shared__ float2 wd2[OC3][9];
    __shared__ __align__(16) float pws[2][HLW * 18];   // 648 each

    const int tid = threadIdx.x;
    const int bd = blockIdx.y;
    const int b = bd / DD, d = bd - b * DD;
    const int tx = blockIdx.x & 3, ty = blockIdx.x >> 2;
    const int h0 = ty * 16, w0 = tx * 32;

    for (int i = tid; i < OC3 * 16; i += 256) {
        float w = wqkv[i]; wq2[i >> 4][i & 15] = make_float2(w, w);
    }
    for (int i = tid; i < OC3 * 9; i += 256) {
        float w = wdw[i]; wd2[i / 9][i % 9] = make_float2(w, w);
    }

    u64 xr0[16], xr1[16];
    k1_load_slot(xr0, tid, b, d, h0, w0, x);
    const bool slot1 = (tid < NPAIR - 256);
    if (slot1) k1_load_slot(xr1, tid + 256, b, d, h0, w0, x);

    const int oy = tid >> 4;
    const int ox = (tid & 15) * 2;

    __syncthreads();

    for (int oc = 0; oc < OC3; oc++) {
        float* pwb = pws[oc & 1];
        // pointwise from registers
        {
            u64 acc = 0ULL;
#pragma unroll
            for (int i = 0; i < 16; i++) fma2(acc, xr0[i], *(const u64*)&wq2[oc][i]);
            *(u64*)&pwb[2 * tid] = acc;
            if (slot1) {
                u64 acc1 = 0ULL;
#pragma unroll
                for (int i = 0; i < 16; i++) fma2(acc1, xr1[i], *(const u64*)&wq2[oc][i]);
                *(u64*)&pwb[2 * (tid + 256)] = acc1;
            }
        }
        __syncthreads();
        // depthwise 3x3: taps at halo cols ox+1..ox+4 (halo col0 = w0-2)
        u64 acc = 0ULL;
#pragma unroll
        for (int dy = 0; dy < 3; dy++) {
            const float* row = pwb + (oy + dy) * HLW + ox;
            u64 av = *(const u64*)row;          // hx ox,   ox+1
            u64 bv = *(const u64*)(row + 2);    // hx ox+2, ox+3
            u64 cv = *(const u64*)(row + 4);    // hx ox+4, ox+5
            u64 mv1 = (av >> 32) | (bv << 32);  // hx ox+1, ox+2  (left tap)
            u64 mv2 = (bv >> 32) | (cv << 32);  // hx ox+3, ox+4  (right tap)
            fma2(acc, mv1, *(const u64*)&wd2[oc][3 * dy + 0]);
            fma2(acc, bv,  *(const u64*)&wd2[oc][3 * dy + 1]);
            fma2(acc, mv2, *(const u64*)&wd2[oc][3 * dy + 2]);
        }
        float* dst; int m;
        if (oc < 16)      { dst = g_q; m = oc * DD + d; }
        else if (oc < 32) { dst = g_k; m = (oc - 16) * DD + d; }
        else              { dst = g_v; m = (oc - 32) * DD + d; }
        *(u64*)&dst[((size_t)(b * MCH) + m) * HWSZ + (h0 + oy) * WW + w0 + ox] = acc;
        // no second barrier: double-buffered pws
    }
}

// ---------------- K2: Gram matrix + norms ----------------------------------
// 256 blocks (64 px-chunks x 4 batches). 256 threads: kg(8) x tc2(8) x tc1(4).
#define K2PITCH 260
#define SMEM2 (2 * 32 * K2PITCH * 4)

__global__ void __launch_bounds__(256, 2) k2_gram() {
    extern __shared__ float sm2[];
    float* qs = sm2;                    // [32][260]
    float* ks = sm2 + 32 * K2PITCH;     // [32][260]

    const int tid = threadIdx.x;
    const int kg  = tid & 7;
    const int tc2 = (tid >> 3) & 7;
    const int tc1 = tid >> 6;
    const int b = blockIdx.y;
    const int hw0 = blockIdx.x * 256;

    const int lrow = tid >> 3;
    const int lc8  = tid & 7;

    u64 acc[32];
#pragma unroll
    for (int i = 0; i < 32; i++) acc[i] = 0ULL;
    float nq_acc = 0.f, nk_acc = 0.f;

    for (int r = 0; r < 16; r++) {
        if (r) __syncthreads();
        {
            const bool valid = (lrow < NCH);
            size_t goff = ((size_t)(b * MCH) + 16 * lrow + r) * HWSZ + hw0;
#pragma unroll
            for (int kk = 0; kk < 8; kk++) {
                int f4 = lc8 + 8 * kk;
                float4 qv = make_float4(0.f, 0.f, 0.f, 0.f);
                float4 kv = make_float4(0.f, 0.f, 0.f, 0.f);
                if (valid) {
                    qv = *(const float4*)&g_q[goff + 4 * f4];
                    kv = *(const float4*)&g_k[goff + 4 * f4];
                }
                *(float4*)&qs[lrow * K2PITCH + 4 * f4] = qv;
                *(float4*)&ks[lrow * K2PITCH + 4 * f4] = kv;
                nq_acc += qv.x * qv.x + qv.y * qv.y + qv.z * qv.z + qv.w * qv.w;
                nk_acc += kv.x * kv.x + kv.y * kv.y + kv.z * kv.z + kv.w * kv.w;
            }
        }
        __syncthreads();
        for (int jj = 0; jj < 16; jj++) {
            int px = 2 * kg + 16 * jj;
            u64 qa[8], kv[4];
#pragma unroll
            for (int a = 0; a < 8; a++) qa[a] = *(const u64*)&qs[(tc1 * 8 + a) * K2PITCH + px];
#pragma unroll
            for (int c = 0; c < 4; c++) kv[c] = *(const u64*)&ks[(tc2 * 4 + c) * K2PITCH + px];
#pragma unroll
            for (int a = 0; a < 8; a++)
#pragma unroll
                for (int c = 0; c < 4; c++)
                    fma2(acc[a * 4 + c], qa[a], kv[c]);
        }
    }

    nq_acc += __shfl_xor_sync(0xffffffffu, nq_acc, 1);
    nq_acc += __shfl_xor_sync(0xffffffffu, nq_acc, 2);
    nq_acc += __shfl_xor_sync(0xffffffffu, nq_acc, 4);
    nk_acc += __shfl_xor_sync(0xffffffffu, nk_acc, 1);
    nk_acc += __shfl_xor_sync(0xffffffffu, nk_acc, 2);
    nk_acc += __shfl_xor_sync(0xffffffffu, nk_acc, 4);
    if (lc8 == 0 && lrow < NCH) {
        atomicAdd(&g_nq[b * NCH + lrow], nq_acc);
        atomicAdd(&g_nk[b * NCH + lrow], nk_acc);
    }

#pragma unroll
    for (int e = 0; e < 32; e++) {
        float2 f = unpack2(acc[e]);
        float s = f.x + f.y;
        s += __shfl_xor_sync(0xffffffffu, s, 1);
        s += __shfl_xor_sync(0xffffffffu, s, 2);
        s += __shfl_xor_sync(0xffffffffu, s, 4);
        if (kg == 0) {
            int row = tc1 * 8 + (e >> 2);
            int col = tc2 * 4 + (e & 3);
            if (row < NCH && col < NCH)
                atomicAdd(&g_sqk[b * NCH * NCH + row * NCH + col], s);
        }
    }
}

// ---------------- K3: softmax (one block per output row) --------------------
__global__ void k3_softmax(const float* __restrict__ temperature) {
    const int b = blockIdx.y, c1 = blockIdx.x, lane = threadIdx.x;
    const float temp = temperature[0];
    float nq = fmaxf(sqrtf(g_nq[b * NCH + c1]), 1e-12f);
    float logit = -1e30f;
    if (lane < NCH) {
        float nk = fmaxf(sqrtf(g_nk[b * NCH + lane]), 1e-12f);
        logit = g_sqk[(b * NCH + c1) * NCH + lane] / (nq * nk) * temp;
    }
    float mx = logit;
#pragma unroll
    for (int s = 16; s; s >>= 1) mx = fmaxf(mx, __shfl_xor_sync(0xffffffffu, mx, s));
    float e = (lane < NCH) ? expf(logit - mx) : 0.f;
    float sum = e;
#pragma unroll
    for (int s = 16; s; s >>= 1) sum += __shfl_xor_sync(0xffffffffu, sum, s);
    if (lane < NCH) g_attn[(b * NCH + c1) * NCH + lane] = e / sum;
}

// ---------------- K4: out = attn @ V then 16x16 projection ------------------
#define OAPITCH 32
#define SMEM4 ((MCH * OAPITCH) * 4 + (NCH * 32) * 8 + 256 * 4)

__global__ void __launch_bounds__(256, 2)
k4_out(const float* __restrict__ wproj, float* __restrict__ out) {
    extern __shared__ float sm4[];
    float* oa = sm4;                                  // [496][32]
    float2* attn2 = (float2*)(sm4 + MCH * OAPITCH);   // [31][32] dup pairs
    float* wp_s = sm4 + MCH * OAPITCH + NCH * 32 * 2; // [256]

    const int tid = threadIdx.x;
    const int b = blockIdx.y;
    const int hw0 = blockIdx.x * 32;

    for (int i = tid; i < NCH * NCH; i += 256) {
        int c1 = i / NCH, dc = i - c1 * NCH;
        float a = g_attn[b * NCH * NCH + i];
        attn2[c1 * 32 + dc] = make_float2(a, a);
    }
    wp_s[tid] = wproj[tid];
    __syncthreads();

    // ---- stage 1: oa[16c+r][px] = sum_dc attn[c][dc] * v[16dc+r][px]
    {
        const int pxp = tid & 15, r = tid >> 4;
        const float* vbase = g_v + ((size_t)(b * MCH) + r) * HWSZ + hw0 + 2 * pxp;
        u64 acc[31];
#pragma unroll
        for (int c = 0; c < 31; c++) acc[c] = 0ULL;

        u64 v0 = *(const u64*)(vbase);
        u64 v1 = *(const u64*)(vbase + 16 * HWSZ);
        for (int j = 0; j < 15; j++) {
            int dc = 2 * j;
            u64 n0 = 0ULL, n1 = 0ULL;
            if (j < 14) {
                n0 = *(const u64*)(vbase + (size_t)16 * (dc + 2) * HWSZ);
                n1 = *(const u64*)(vbase + (size_t)16 * (dc + 3) * HWSZ);
            } else {
                n0 = *(const u64*)(vbase + (size_t)16 * 30 * HWSZ);
            }
#pragma unroll
            for (int c = 0; c < 31; c++) {
                ulonglong2 at = *(const ulonglong2*)&attn2[c * 32 + dc];
                fma2(acc[c], v0, at.x);
                fma2(acc[c], v1, at.y);
            }
            v0 = n0; v1 = n1;
        }
#pragma unroll
        for (int c = 0; c < 31; c++) {
            u64 a30 = *(const u64*)&attn2[c * 32 + 30];
            fma2(acc[c], v0, a30);
        }
#pragma unroll
        for (int c = 0; c < 31; c++)
            *(u64*)&oa[(16 * c + r) * OAPITCH + 2 * pxp] = acc[c];
    }
    __syncthreads();

    // ---- stage 2: out[o*31+ds][px] = sum_i wp[o][i] * oa[i*31+ds][px]
    {
        const int pxp = tid & 15;
        const int oo = (tid >> 4) & 7;
        const int dsg = tid >> 7;
        const int o0 = 2 * oo, o1 = 2 * oo + 1;
        u64 wpa[16], wpb[16];
#pragma unroll
        for (int i = 0; i < 16; i++) {
            float wa = wp_s[o0 * 16 + i], wb = wp_s[o1 * 16 + i];
            wpa[i] = pack2(wa, wa);
            wpb[i] = pack2(wb, wb);
        }
        for (int ds = dsg; ds < NCH; ds += 2) {
            u64 a0 = 0ULL, a1 = 0ULL;
#pragma unroll
            for (int i = 0; i < 16; i++) {
                u64 ov = *(const u64*)&oa[(i * NCH + ds) * OAPITCH + 2 * pxp];
                fma2(a0, ov, wpa[i]);
                fma2(a1, ov, wpb[i]);
            }
            size_t obase = ((size_t)((b * 16 + o0) * DD + ds)) * HWSZ + hw0 + 2 * pxp;
            *(u64*)&out[obase] = a0;
            *(u64*)&out[obase + (size_t)DD * HWSZ] = a1;
        }
    }
}

// ---------------- launch -----------------------------------------------------
extern "C" void kernel_launch(void* const* d_in, const int* in_sizes, int n_in,
                              void* d_out, int out_size) {
    const float* x     = (const float*)d_in[0];
    const float* wqkv  = (const float*)d_in[1];
    const float* wdw   = (const float*)d_in[2];
    const float* wproj = (const float*)d_in[3];
    const float* temp  = (const float*)d_in[4];
    float* out = (float*)d_out;

    cudaFuncSetAttribute(k2_gram, cudaFuncAttributeMaxDynamicSharedMemorySize, SMEM2);
    cudaFuncSetAttribute(k4_out,  cudaFuncAttributeMaxDynamicSharedMemorySize, SMEM4);

    k0_zero<<<16, 256>>>();

    dim3 g1(32, BB * DD);
    k1_qkv<<<g1, 256>>>(x, wqkv, wdw);

    dim3 g2(64, BB);
    k2_gram<<<g2, 256, SMEM2>>>();

    dim3 g3(NCH, BB);
    k3_softmax<<<g3, 32>>>(temp);

    dim3 g4(HWSZ / 32, BB);
    k4_out<<<g4, 256, SMEM4>>>(wproj, out);
}